// round 8
// baseline (speedup 1.0000x reference)
#include <cuda_runtime.h>
#include <cstdint>

#define BB 8
#define CC 256
#define OO 256
#define HH 64
#define WW 64
#define DGRP 4
#define CG 64
#define KK2 9
#define CK 2304      /* C*K2 */
#define HWP 4096     /* H*W */
#define MTOT (BB * HWP)   /* 32768 */

// ---------------- scratch (device globals; no cudaMalloc allowed) ----------------
__device__ __align__(256) float g_xT[(size_t)BB * DGRP * HWP * CG];   // 32 MB
__device__ __align__(256) float g_col[(size_t)MTOT * CK];             // 302 MB (tf32-rounded)
__device__ __align__(256) float g_wK[(size_t)OO * CK];                // 2.36 MB, [o][ck] K-major
__device__ __align__(256) float g_y[(size_t)MTOT * OO];               // 32 MB, conv out (NHWC)

// ---------------- helpers ----------------
__device__ __forceinline__ uint32_t smem_u32(const void* p) {
    uint32_t a;
    asm("{ .reg .u64 t; cvta.to.shared.u64 t, %1; cvt.u32.u64 %0, t; }" : "=r"(a) : "l"(p));
    return a;
}
__device__ __forceinline__ float to_tf32(float x) {
    uint32_t u;
    asm("cvt.rna.tf32.f32 %0, %1;" : "=r"(u) : "f"(x));
    return __uint_as_float(u);
}
__device__ __forceinline__ void cp16(uint32_t dst, const void* src) {
    asm volatile("cp.async.cg.shared.global [%0], [%1], 16;" :: "r"(dst), "l"(src));
}
__device__ __forceinline__ void ldsm4(uint32_t& r0, uint32_t& r1, uint32_t& r2,
                                      uint32_t& r3, uint32_t addr) {
    asm volatile("ldmatrix.sync.aligned.m8n8.x4.shared.b16 {%0,%1,%2,%3}, [%4];"
                 : "=r"(r0), "=r"(r1), "=r"(r2), "=r"(r3) : "r"(addr));
}
__device__ __forceinline__ void mma_tf32(float* d, const uint32_t* a, const uint32_t* b) {
    asm volatile(
        "mma.sync.aligned.m16n8k8.row.col.f32.tf32.tf32.f32 "
        "{%0,%1,%2,%3}, {%4,%5,%6,%7}, {%8,%9}, {%0,%1,%2,%3};"
        : "+f"(d[0]), "+f"(d[1]), "+f"(d[2]), "+f"(d[3])
        : "r"(a[0]), "r"(a[1]), "r"(a[2]), "r"(a[3]), "r"(b[0]), "r"(b[1]));
}

// ---------------- kernel 1: weights -> g_wK[o][ck] (K-major, tf32-rounded) ----------------
__global__ void wprep_kernel(const float* __restrict__ wd) {
    int idx = blockIdx.x * 256 + threadIdx.x;   // < OO*CK
    int o = idx / CK;
    int ck = idx - o * CK;
    int cg = ck & 63;
    int t = ck >> 6;
    int k2 = t % KK2;
    int g = t / KK2;
    g_wK[idx] = to_tf32(wd[((size_t)o * CC + g * CG + cg) * KK2 + k2]);
}

// ---------------- kernel 2: x[b][c][p] -> xT[b][g][p][cg] ----------------
__global__ void transpose_kernel(const float* __restrict__ x) {
    __shared__ float tile[32][33];
    int bg = blockIdx.z;
    int c0 = blockIdx.y * 32;
    int p0 = blockIdx.x * 32;
    int tx = threadIdx.x, ty = threadIdx.y;
    const float* in = x + (size_t)bg * CG * HWP;
    float* out = g_xT + (size_t)bg * HWP * CG;
#pragma unroll
    for (int i = 0; i < 32; i += 8)
        tile[ty + i][tx] = in[(size_t)(c0 + ty + i) * HWP + p0 + tx];
    __syncthreads();
#pragma unroll
    for (int i = 0; i < 32; i += 8)
        out[(size_t)(p0 + ty + i) * CG + c0 + tx] = tile[tx][ty + i];
}

// ---------------- kernel 3: offsets (1x1 conv) + deformable im2col ----------------
// one warp per (b, g, p); handles all 9 kernel points
__global__ void im2col_kernel(const float* __restrict__ x_off,
                              const float* __restrict__ w_offset) {
    int tid = threadIdx.x;
    int lane = tid & 31;
    int wi = blockIdx.x * 8 + (tid >> 5);   // < 131072 = B*DG*HW
    int p = wi & (HWP - 1);
    int t2 = wi >> 12;
    int g = t2 & 3;
    int b = t2 >> 2;
    int h = p >> 6, w = p & 63;

    const float* xo = x_off + (size_t)b * 4 * HWP + p;
    float ov = (lane < 4) ? xo[(size_t)lane * HWP] : 0.f;
    float o0 = __shfl_sync(0xFFFFFFFFu, ov, 0);
    float o1 = __shfl_sync(0xFFFFFFFFu, ov, 1);
    float o2 = __shfl_sync(0xFFFFFFFFu, ov, 2);
    float o3 = __shfl_sync(0xFFFFFFFFu, ov, 3);

    float comp = 0.f;
    if (lane < 18) {
        int k2c = lane % 9;
        int ax = lane / 9;
        const float* wo = w_offset + (size_t)(((g * KK2 + k2c) * 2 + ax)) * 4;
        comp = wo[0] * o0 + wo[1] * o1 + wo[2] * o2 + wo[3] * o3;
    }

    const float* base = g_xT + (size_t)(b * DGRP + g) * HWP * CG;
    float* dstbase = g_col + (size_t)(b * HWP + p) * CK + g * KK2 * CG;

#pragma unroll
    for (int k2 = 0; k2 < KK2; k2++) {
        float offy = __shfl_sync(0xFFFFFFFFu, comp, k2);
        float offx = __shfl_sync(0xFFFFFFFFu, comp, k2 + 9);
        float py = (float)(h + k2 / 3 - 1) + offy;
        float px = (float)(w + k2 % 3 - 1) + offx;
        float fy = floorf(py), fx = floorf(px);
        float wy = py - fy, wx = px - fx;
        int y0 = (int)fy, x0 = (int)fx;

        float w00 = (1.f - wy) * (1.f - wx);
        float w01 = (1.f - wy) * wx;
        float w10 = wy * (1.f - wx);
        float w11 = wy * wx;

        bool vy0 = (y0 >= 0) & (y0 < HH);
        bool vy1 = (y0 + 1 >= 0) & (y0 + 1 < HH);
        bool vx0 = (x0 >= 0) & (x0 < WW);
        bool vx1 = (x0 + 1 >= 0) & (x0 + 1 < WW);
        if (!(vy0 && vx0)) w00 = 0.f;
        if (!(vy0 && vx1)) w01 = 0.f;
        if (!(vy1 && vx0)) w10 = 0.f;
        if (!(vy1 && vx1)) w11 = 0.f;

        int y0c = min(max(y0, 0), HH - 1), y1c = min(max(y0 + 1, 0), HH - 1);
        int x0c = min(max(x0, 0), WW - 1), x1c = min(max(x0 + 1, 0), WW - 1);

        const float* p00 = base + (size_t)(y0c * WW + x0c) * CG;
        const float* p01 = base + (size_t)(y0c * WW + x1c) * CG;
        const float* p10 = base + (size_t)(y1c * WW + x0c) * CG;
        const float* p11 = base + (size_t)(y1c * WW + x1c) * CG;

        float* dst = dstbase + k2 * CG;
#pragma unroll
        for (int rep = 0; rep < 2; rep++) {
            int cg = lane + rep * 32;
            float v = w00 * p00[cg] + w01 * p01[cg] + w10 * p10[cg] + w11 * p11[cg];
            dst[cg] = to_tf32(v);
        }
    }
}

// ---------------- kernel 4: tf32 mma.sync GEMM  y[m][o] = col[m][:] . wK[o][:] ----------------
// block 128x256 (full N), BK=32, 8 warps (2x4), warp tile 64x64
// ldmatrix.x4 fragment loads, 3-stage cp.async ring, single wave (256 CTAs)
#define BK 32
#define LDT 36
#define NST (CK / BK)   /* 72 */
#define NSTAGE 3
#define A_STG_F (128 * LDT)
#define B_STG_F (256 * LDT)
#define GEMM_SMEM (NSTAGE * (A_STG_F + B_STG_F) * 4)   /* 165888 B */

__global__ __launch_bounds__(256, 1) void gemm_kernel() {
    extern __shared__ __align__(16) float dsm[];
    float* Asm = dsm;
    float* Bsm = dsm + NSTAGE * A_STG_F;
    uint32_t sA0 = smem_u32(Asm);
    uint32_t sB0 = smem_u32(Bsm);

    int tid = threadIdx.x;
    int m0 = blockIdx.x * 128;

    int lane = tid & 31, w = tid >> 5;
    int wm = (w >> 2) * 64;   // warp m-offset (0/64)
    int wn = (w & 3) * 64;    // warp n-offset (0/64/128/192)
    int g = lane >> 2, tq = lane & 3;

    // ldmatrix per-lane source offsets (floats)
    int sector = lane >> 3, rowin = lane & 7;
    int aoff[4], boff[4];
#pragma unroll
    for (int i = 0; i < 4; i++)
        aoff[i] = (wm + i * 16 + (sector & 1) * 8 + rowin) * LDT + (sector >> 1) * 4;
#pragma unroll
    for (int jp = 0; jp < 4; jp++)
        boff[jp] = (wn + (jp * 2 + (sector >> 1)) * 8 + rowin) * LDT + (sector & 1) * 4;

    // cp.async tasks: A = 128 rows x 8 chunks(16B) = 1024; B = 256 x 8 = 2048
    int ar[4], ac[4], br[8], bc[8];
#pragma unroll
    for (int q = 0; q < 4; q++) {
        int task = tid + q * 256;
        ar[q] = task >> 3;
        ac[q] = (task & 7) * 4;
    }
#pragma unroll
    for (int q = 0; q < 8; q++) {
        int task = tid + q * 256;
        br[q] = task >> 3;
        bc[q] = (task & 7) * 4;
    }

    float acc[4][8][4];
#pragma unroll
    for (int i = 0; i < 4; i++)
#pragma unroll
        for (int jj = 0; jj < 8; jj++)
#pragma unroll
            for (int e = 0; e < 4; e++) acc[i][jj][e] = 0.f;

    // ---- prologue: stages 0,1 ----
#pragma unroll
    for (int s = 0; s < NSTAGE - 1; s++) {
        int k0 = s * BK;
        uint32_t a_base = sA0 + (uint32_t)(s * A_STG_F * 4);
        uint32_t b_base = sB0 + (uint32_t)(s * B_STG_F * 4);
#pragma unroll
        for (int q = 0; q < 4; q++)
            cp16(a_base + (uint32_t)(ar[q] * LDT + ac[q]) * 4,
                 g_col + (size_t)(m0 + ar[q]) * CK + k0 + ac[q]);
#pragma unroll
        for (int q = 0; q < 8; q++)
            cp16(b_base + (uint32_t)(br[q] * LDT + bc[q]) * 4,
                 g_wK + (size_t)br[q] * CK + k0 + bc[q]);
        asm volatile("cp.async.commit_group;" ::: "memory");
    }

    int buf = 0;
    for (int s = 0; s < NST; s++) {
        if (s + 1 < NST) {
            asm volatile("cp.async.wait_group 1;" ::: "memory");
        } else {
            asm volatile("cp.async.wait_group 0;" ::: "memory");
        }
        __syncthreads();

        if (s + 2 < NST) {
            int nb = buf + 2 >= NSTAGE ? buf + 2 - NSTAGE : buf + 2;
            int k0 = (s + 2) * BK;
            uint32_t a_base = sA0 + (uint32_t)(nb * A_STG_F * 4);
            uint32_t b_base = sB0 + (uint32_t)(nb * B_STG_F * 4);
#pragma unroll
            for (int q = 0; q < 4; q++)
                cp16(a_base + (uint32_t)(ar[q] * LDT + ac[q]) * 4,
                     g_col + (size_t)(m0 + ar[q]) * CK + k0 + ac[q]);
#pragma unroll
            for (int q = 0; q < 8; q++)
                cp16(b_base + (uint32_t)(br[q] * LDT + bc[q]) * 4,
                     g_wK + (size_t)br[q] * CK + k0 + bc[q]);
            asm volatile("cp.async.commit_group;" ::: "memory");
        }

        uint32_t abuf = sA0 + (uint32_t)(buf * A_STG_F * 4);
        uint32_t bbuf = sB0 + (uint32_t)(buf * B_STG_F * 4);
#pragma unroll
        for (int ks = 0; ks < 4; ks++) {
            uint32_t af[4][4], bf[8][2];
            uint32_t kofs = (uint32_t)(ks * 8) * 4;
#pragma unroll
            for (int i = 0; i < 4; i++)
                ldsm4(af[i][0], af[i][1], af[i][2], af[i][3],
                      abuf + kofs + (uint32_t)aoff[i] * 4);
#pragma unroll
            for (int jp = 0; jp < 4; jp++)
                ldsm4(bf[jp * 2][0], bf[jp * 2][1], bf[jp * 2 + 1][0], bf[jp * 2 + 1][1],
                      bbuf + kofs + (uint32_t)boff[jp] * 4);
#pragma unroll
            for (int i = 0; i < 4; i++)
#pragma unroll
                for (int jj = 0; jj < 8; jj++) mma_tf32(acc[i][jj], af[i], bf[jj]);
        }

        buf = buf + 1 >= NSTAGE ? 0 : buf + 1;
    }

    // ---- epilogue: write y (NHWC rows of 256) ----
#pragma unroll
    for (int i = 0; i < 4; i++) {
#pragma unroll
        for (int jj = 0; jj < 8; jj++) {
            int row = m0 + wm + i * 16 + g;
            int col = wn + jj * 8 + 2 * tq;
            float2 v0 = make_float2(acc[i][jj][0], acc[i][jj][1]);
            float2 v1 = make_float2(acc[i][jj][2], acc[i][jj][3]);
            *(float2*)(g_y + (size_t)row * OO + col) = v0;
            *(float2*)(g_y + (size_t)(row + 8) * OO + col) = v1;
        }
    }
}

// ---------------- kernel 5: GroupNorm + ReLU + NHWC->NCHW (smem-staged) ----------------
__global__ void gn_kernel(const float* __restrict__ gamma,
                          const float* __restrict__ beta, float* __restrict__ out) {
    int b = blockIdx.x >> 5;
    int gi = blockIdx.x & 31;
    int tid = threadIdx.x;   // 256
    const float* yb = g_y + (size_t)b * HWP * OO;

    float s = 0.f, ss = 0.f;
    for (int e4 = tid; e4 < 8192; e4 += 256) {
        int p = e4 >> 1, j4 = e4 & 1;
        float4 v = *(const float4*)(yb + (size_t)p * OO + gi * 8 + j4 * 4);
        s += v.x + v.y + v.z + v.w;
        ss += v.x * v.x + v.y * v.y + v.z * v.z + v.w * v.w;
    }
    __shared__ float rs[256], rss[256];
    rs[tid] = s;
    rss[tid] = ss;
    __syncthreads();
    for (int st = 128; st > 0; st >>= 1) {
        if (tid < st) {
            rs[tid] += rs[tid + st];
            rss[tid] += rss[tid + st];
        }
        __syncthreads();
    }
    float mu = rs[0] * (1.f / 32768.f);
    float var = rss[0] * (1.f / 32768.f) - mu * mu;
    float rstd = rsqrtf(var + 1e-5f);

    float ga[8], be[8];
#pragma unroll
    for (int j = 0; j < 8; j++) {
        int o = gi * 8 + j;
        ga[j] = gamma[o] * rstd;
        be[j] = beta[o] - mu * ga[j];
    }

    __shared__ float stb[8 * 520];   // [ch][520]
    for (int p0 = 0; p0 < HWP; p0 += 512) {
#pragma unroll
        for (int q = 0; q < 2; q++) {
            int pp = tid * 2 + q;   // 0..511
            const float* src = yb + (size_t)(p0 + pp) * OO + gi * 8;
            float4 v0 = *(const float4*)src;
            float4 v1 = *(const float4*)(src + 4);
            float r[8] = {v0.x, v0.y, v0.z, v0.w, v1.x, v1.y, v1.z, v1.w};
#pragma unroll
            for (int j = 0; j < 8; j++)
                stb[j * 520 + pp] = fmaxf(fmaf(r[j], ga[j], be[j]), 0.f);
        }
        __syncthreads();
#pragma unroll
        for (int q = 0; q < 4; q++) {
            int idx = tid + q * 256;
            int ch = idx >> 7, p4 = (idx & 127) * 4;
            float4 v = *(float4*)&stb[ch * 520 + p4];
            *(float4*)(out + (size_t)(b * OO + gi * 8 + ch) * HWP + p0 + p4) = v;
        }
        __syncthreads();
    }
}

// ---------------- launch ----------------
extern "C" void kernel_launch(void* const* d_in, const int* in_sizes, int n_in,
                              void* d_out, int out_size) {
    const float* x        = (const float*)d_in[0];
    const float* x_off    = (const float*)d_in[1];
    const float* w_offset = (const float*)d_in[2];
    const float* w_deform = (const float*)d_in[3];
    const float* gamma    = (const float*)d_in[4];
    const float* beta     = (const float*)d_in[5];
    float* out = (float*)d_out;

    cudaFuncSetAttribute(gemm_kernel, cudaFuncAttributeMaxDynamicSharedMemorySize,
                         GEMM_SMEM);

    wprep_kernel<<<OO * CK / 256, 256>>>(w_deform);

    dim3 tb(32, 8), tg(HWP / 32, CG / 32, BB * DGRP);
    transpose_kernel<<<tg, tb>>>(x);

    im2col_kernel<<<16384, 256>>>(x_off, w_offset);

    gemm_kernel<<<MTOT / 128, 256, GEMM_SMEM>>>();

    gn_kernel<<<BB * 32, 256>>>(gamma, beta, out);
}

// round 10
// speedup vs baseline: 1.4197x; 1.4197x over previous
#include <cuda_runtime.h>
#include <cuda_fp16.h>
#include <cstdint>

#define BB 8
#define CC 256
#define OO 256
#define HH 64
#define WW 64
#define DGRP 4
#define CG 64
#define KK2 9
#define CK 2304      /* C*K2 */
#define HWP 4096     /* H*W */
#define MTOT (BB * HWP)   /* 32768 */

// ---------------- scratch (device globals; no cudaMalloc allowed) ----------------
__device__ __align__(256) float  g_xT[(size_t)BB * DGRP * HWP * CG];   // 32 MB
__device__ __align__(256) __half g_col[(size_t)MTOT * CK];             // 151 MB fp16
__device__ __align__(256) __half g_wK[(size_t)OO * CK];                // 1.2 MB, [o][ck] K-major
__device__ __align__(256) float  g_y[(size_t)MTOT * OO];               // 32 MB, conv out (NHWC)

// ---------------- helpers ----------------
__device__ __forceinline__ uint32_t smem_u32(const void* p) {
    uint32_t a;
    asm("{ .reg .u64 t; cvta.to.shared.u64 t, %1; cvt.u32.u64 %0, t; }" : "=r"(a) : "l"(p));
    return a;
}
__device__ __forceinline__ void cp16(uint32_t dst, const void* src) {
    asm volatile("cp.async.cg.shared.global [%0], [%1], 16;" :: "r"(dst), "l"(src));
}
__device__ __forceinline__ void ldsm4(uint32_t& r0, uint32_t& r1, uint32_t& r2,
                                      uint32_t& r3, uint32_t addr) {
    asm volatile("ldmatrix.sync.aligned.m8n8.x4.shared.b16 {%0,%1,%2,%3}, [%4];"
                 : "=r"(r0), "=r"(r1), "=r"(r2), "=r"(r3) : "r"(addr));
}
__device__ __forceinline__ void mma_fp16(float* d, const uint32_t* a, const uint32_t* b) {
    asm volatile(
        "mma.sync.aligned.m16n8k16.row.col.f32.f16.f16.f32 "
        "{%0,%1,%2,%3}, {%4,%5,%6,%7}, {%8,%9}, {%0,%1,%2,%3};"
        : "+f"(d[0]), "+f"(d[1]), "+f"(d[2]), "+f"(d[3])
        : "r"(a[0]), "r"(a[1]), "r"(a[2]), "r"(a[3]), "r"(b[0]), "r"(b[1]));
}

// ---------------- kernel 1: weights -> g_wK[o][ck] (K-major, fp16) ----------------
__global__ void wprep_kernel(const float* __restrict__ wd) {
    int idx = blockIdx.x * 256 + threadIdx.x;   // < OO*CK
    int o = idx / CK;
    int ck = idx - o * CK;
    int cg = ck & 63;
    int t = ck >> 6;
    int k2 = t % KK2;
    int g = t / KK2;
    g_wK[idx] = __float2half_rn(wd[((size_t)o * CC + g * CG + cg) * KK2 + k2]);
}

// ---------------- kernel 2: x[b][c][p] -> xT[b][g][p][cg] ----------------
__global__ void transpose_kernel(const float* __restrict__ x) {
    __shared__ float tile[32][33];
    int bg = blockIdx.z;
    int c0 = blockIdx.y * 32;
    int p0 = blockIdx.x * 32;
    int tx = threadIdx.x, ty = threadIdx.y;
    const float* in = x + (size_t)bg * CG * HWP;
    float* out = g_xT + (size_t)bg * HWP * CG;
#pragma unroll
    for (int i = 0; i < 32; i += 8)
        tile[ty + i][tx] = in[(size_t)(c0 + ty + i) * HWP + p0 + tx];
    __syncthreads();
#pragma unroll
    for (int i = 0; i < 32; i += 8)
        out[(size_t)(p0 + ty + i) * CG + c0 + tx] = tile[tx][ty + i];
}

// ---------------- kernel 3: offsets (1x1 conv) + deformable im2col (fp16 out) --------
// one warp per (b, g, p); handles all 9 kernel points; lane owns channel pair 2l,2l+1
__global__ void im2col_kernel(const float* __restrict__ x_off,
                              const float* __restrict__ w_offset) {
    int tid = threadIdx.x;
    int lane = tid & 31;
    int wi = blockIdx.x * 8 + (tid >> 5);   // < 131072 = B*DG*HW
    int p = wi & (HWP - 1);
    int t2 = wi >> 12;
    int g = t2 & 3;
    int b = t2 >> 2;
    int h = p >> 6, w = p & 63;

    const float* xo = x_off + (size_t)b * 4 * HWP + p;
    float ov = (lane < 4) ? xo[(size_t)lane * HWP] : 0.f;
    float o0 = __shfl_sync(0xFFFFFFFFu, ov, 0);
    float o1 = __shfl_sync(0xFFFFFFFFu, ov, 1);
    float o2 = __shfl_sync(0xFFFFFFFFu, ov, 2);
    float o3 = __shfl_sync(0xFFFFFFFFu, ov, 3);

    float comp = 0.f;
    if (lane < 18) {
        int k2c = lane % 9;
        int ax = lane / 9;
        const float* wo = w_offset + (size_t)(((g * KK2 + k2c) * 2 + ax)) * 4;
        comp = wo[0] * o0 + wo[1] * o1 + wo[2] * o2 + wo[3] * o3;
    }

    const float* base = g_xT + (size_t)(b * DGRP + g) * HWP * CG;
    __half* dstbase = g_col + (size_t)(b * HWP + p) * CK + g * KK2 * CG;

#pragma unroll
    for (int k2 = 0; k2 < KK2; k2++) {
        float offy = __shfl_sync(0xFFFFFFFFu, comp, k2);
        float offx = __shfl_sync(0xFFFFFFFFu, comp, k2 + 9);
        float py = (float)(h + k2 / 3 - 1) + offy;
        float px = (float)(w + k2 % 3 - 1) + offx;
        float fy = floorf(py), fx = floorf(px);
        float wy = py - fy, wx = px - fx;
        int y0 = (int)fy, x0 = (int)fx;

        float w00 = (1.f - wy) * (1.f - wx);
        float w01 = (1.f - wy) * wx;
        float w10 = wy * (1.f - wx);
        float w11 = wy * wx;

        bool vy0 = (y0 >= 0) & (y0 < HH);
        bool vy1 = (y0 + 1 >= 0) & (y0 + 1 < HH);
        bool vx0 = (x0 >= 0) & (x0 < WW);
        bool vx1 = (x0 + 1 >= 0) & (x0 + 1 < WW);
        if (!(vy0 && vx0)) w00 = 0.f;
        if (!(vy0 && vx1)) w01 = 0.f;
        if (!(vy1 && vx0)) w10 = 0.f;
        if (!(vy1 && vx1)) w11 = 0.f;

        int y0c = min(max(y0, 0), HH - 1), y1c = min(max(y0 + 1, 0), HH - 1);
        int x0c = min(max(x0, 0), WW - 1), x1c = min(max(x0 + 1, 0), WW - 1);

        const float* p00 = base + (size_t)(y0c * WW + x0c) * CG + 2 * lane;
        const float* p01 = base + (size_t)(y0c * WW + x1c) * CG + 2 * lane;
        const float* p10 = base + (size_t)(y1c * WW + x0c) * CG + 2 * lane;
        const float* p11 = base + (size_t)(y1c * WW + x1c) * CG + 2 * lane;

        float2 t00 = *(const float2*)p00;
        float2 t01 = *(const float2*)p01;
        float2 t10 = *(const float2*)p10;
        float2 t11 = *(const float2*)p11;
        float vx_ = w00 * t00.x + w01 * t01.x + w10 * t10.x + w11 * t11.x;
        float vy_ = w00 * t00.y + w01 * t01.y + w10 * t10.y + w11 * t11.y;

        *(__half2*)(dstbase + k2 * CG + 2 * lane) = __floats2half2_rn(vx_, vy_);
    }
}

// ---------------- kernel 4: fp16 mma.sync GEMM  y[m][o] = col[m][:] . wK[o][:] --------
// block 128x128, BK=64 halves, 8 warps (2x4), warp tile 64x32
// ldmatrix.x4 fragment loads, 3-stage cp.async ring, one barrier per K-step
#define BKH 64
#define LDTH 72
#define NST (CK / BKH)   /* 36 */
#define NSTAGE 3
#define STG_H (128 * LDTH)                  /* halves per operand stage */
#define GEMM_SMEM (NSTAGE * 2 * STG_H * 2)  /* 110592 B */

__global__ __launch_bounds__(256, 2) void gemm_kernel() {
    extern __shared__ __align__(16) __half dsmh[];
    __half* Asm = dsmh;
    __half* Bsm = dsmh + NSTAGE * STG_H;
    uint32_t sA0 = smem_u32(Asm);
    uint32_t sB0 = smem_u32(Bsm);

    int tid = threadIdx.x;
    int n0 = blockIdx.x * 128;
    int m0 = blockIdx.y * 128;

    int lane = tid & 31, w = tid >> 5;
    int wm = (w >> 2) * 64;   // warp m-offset (0/64)
    int wn = (w & 3) * 32;    // warp n-offset (0/32/64/96)
    int g = lane >> 2, tq = lane & 3;

    // ldmatrix per-lane source offsets (halves)
    int sector = lane >> 3, rowin = lane & 7;
    int aoff[4], boff[2];
#pragma unroll
    for (int i = 0; i < 4; i++)
        aoff[i] = (wm + i * 16 + (sector & 1) * 8 + rowin) * LDTH + (sector >> 1) * 8;
#pragma unroll
    for (int jp = 0; jp < 2; jp++)
        boff[jp] = (wn + jp * 16 + (sector & 1) * 8 + rowin) * LDTH + (sector >> 1) * 8;

    // cp.async tasks: tile = 128 rows x 8 chunks(16B = 8 halves) = 1024; 4/thread
    int cr[4], cc[4];
#pragma unroll
    for (int q = 0; q < 4; q++) {
        int task = tid + q * 256;
        cr[q] = task >> 3;
        cc[q] = (task & 7) * 8;   // halves
    }

    float acc[4][4][4];
#pragma unroll
    for (int i = 0; i < 4; i++)
#pragma unroll
        for (int jj = 0; jj < 4; jj++)
#pragma unroll
            for (int e = 0; e < 4; e++) acc[i][jj][e] = 0.f;

    // ---- prologue: stages 0,1 ----
#pragma unroll
    for (int s = 0; s < NSTAGE - 1; s++) {
        int k0 = s * BKH;
        uint32_t a_base = sA0 + (uint32_t)(s * STG_H * 2);
        uint32_t b_base = sB0 + (uint32_t)(s * STG_H * 2);
#pragma unroll
        for (int q = 0; q < 4; q++) {
            cp16(a_base + (uint32_t)(cr[q] * LDTH + cc[q]) * 2,
                 g_col + (size_t)(m0 + cr[q]) * CK + k0 + cc[q]);
            cp16(b_base + (uint32_t)(cr[q] * LDTH + cc[q]) * 2,
                 g_wK + (size_t)(n0 + cr[q]) * CK + k0 + cc[q]);
        }
        asm volatile("cp.async.commit_group;" ::: "memory");
    }

    int buf = 0;
    for (int s = 0; s < NST; s++) {
        if (s + 1 < NST) {
            asm volatile("cp.async.wait_group 1;" ::: "memory");
        } else {
            asm volatile("cp.async.wait_group 0;" ::: "memory");
        }
        __syncthreads();

        if (s + 2 < NST) {
            int nb = buf + 2 >= NSTAGE ? buf + 2 - NSTAGE : buf + 2;
            int k0 = (s + 2) * BKH;
            uint32_t a_base = sA0 + (uint32_t)(nb * STG_H * 2);
            uint32_t b_base = sB0 + (uint32_t)(nb * STG_H * 2);
#pragma unroll
            for (int q = 0; q < 4; q++) {
                cp16(a_base + (uint32_t)(cr[q] * LDTH + cc[q]) * 2,
                     g_col + (size_t)(m0 + cr[q]) * CK + k0 + cc[q]);
                cp16(b_base + (uint32_t)(cr[q] * LDTH + cc[q]) * 2,
                     g_wK + (size_t)(n0 + cr[q]) * CK + k0 + cc[q]);
            }
            asm volatile("cp.async.commit_group;" ::: "memory");
        }

        uint32_t abuf = sA0 + (uint32_t)(buf * STG_H * 2);
        uint32_t bbuf = sB0 + (uint32_t)(buf * STG_H * 2);
#pragma unroll
        for (int ks = 0; ks < 4; ks++) {           // 4 k16-steps per BK=64
            uint32_t af[4][4], q0, q1, q2, q3;
            uint32_t bf[4][2];
            uint32_t kofs = (uint32_t)(ks * 16) * 2;   // bytes
#pragma unroll
            for (int i = 0; i < 4; i++)
                ldsm4(af[i][0], af[i][1], af[i][2], af[i][3],
                      abuf + kofs + (uint32_t)aoff[i] * 2);
#pragma unroll
            for (int jp = 0; jp < 2; jp++) {
                ldsm4(q0, q1, q2, q3, bbuf + kofs + (uint32_t)boff[jp] * 2);
                bf[jp * 2][0] = q0; bf[jp * 2][1] = q2;       // rows n..n+7
                bf[jp * 2 + 1][0] = q1; bf[jp * 2 + 1][1] = q3; // rows n+8..n+15
            }
#pragma unroll
            for (int i = 0; i < 4; i++)
#pragma unroll
                for (int jj = 0; jj < 4; jj++) mma_fp16(acc[i][jj], af[i], bf[jj]);
        }

        buf = buf + 1 >= NSTAGE ? 0 : buf + 1;
    }

    // ---- epilogue: write y (NHWC rows of 256) ----
#pragma unroll
    for (int i = 0; i < 4; i++) {
#pragma unroll
        for (int jj = 0; jj < 4; jj++) {
            int row = m0 + wm + i * 16 + g;
            int col = n0 + wn + jj * 8 + 2 * tq;
            float2 v0 = make_float2(acc[i][jj][0], acc[i][jj][1]);
            float2 v1 = make_float2(acc[i][jj][2], acc[i][jj][3]);
            *(float2*)(g_y + (size_t)row * OO + col) = v0;
            *(float2*)(g_y + (size_t)(row + 8) * OO + col) = v1;
        }
    }
}

// ---------------- kernel 5: GroupNorm + ReLU + NHWC->NCHW (smem-staged) ----------------
__global__ void gn_kernel(const float* __restrict__ gamma,
                          const float* __restrict__ beta, float* __restrict__ out) {
    int b = blockIdx.x >> 5;
    int gi = blockIdx.x & 31;
    int tid = threadIdx.x;   // 256
    const float* yb = g_y + (size_t)b * HWP * OO;

    float s = 0.f, ss = 0.f;
    for (int e4 = tid; e4 < 8192; e4 += 256) {
        int p = e4 >> 1, j4 = e4 & 1;
        float4 v = *(const float4*)(yb + (size_t)p * OO + gi * 8 + j4 * 4);
        s += v.x + v.y + v.z + v.w;
        ss += v.x * v.x + v.y * v.y + v.z * v.z + v.w * v.w;
    }
    __shared__ float rs[256], rss[256];
    rs[tid] = s;
    rss[tid] = ss;
    __syncthreads();
    for (int st = 128; st > 0; st >>= 1) {
        if (tid < st) {
            rs[tid] += rs[tid + st];
            rss[tid] += rss[tid + st];
        }
        __syncthreads();
    }
    float mu = rs[0] * (1.f / 32768.f);
    float var = rss[0] * (1.f / 32768.f) - mu * mu;
    float rstd = rsqrtf(var + 1e-5f);

    float ga[8], be[8];
#pragma unroll
    for (int j = 0; j < 8; j++) {
        int o = gi * 8 + j;
        ga[j] = gamma[o] * rstd;
        be[j] = beta[o] - mu * ga[j];
    }

    __shared__ float stb[8 * 520];   // [ch][520]
    for (int p0 = 0; p0 < HWP; p0 += 512) {
#pragma unroll
        for (int q = 0; q < 2; q++) {
            int pp = tid * 2 + q;   // 0..511
            const float* src = yb + (size_t)(p0 + pp) * OO + gi * 8;
            float4 v0 = *(const float4*)src;
            float4 v1 = *(const float4*)(src + 4);
            float r[8] = {v0.x, v0.y, v0.z, v0.w, v1.x, v1.y, v1.z, v1.w};
#pragma unroll
            for (int j = 0; j < 8; j++)
                stb[j * 520 + pp] = fmaxf(fmaf(r[j], ga[j], be[j]), 0.f);
        }
        __syncthreads();
#pragma unroll
        for (int q = 0; q < 4; q++) {
            int idx = tid + q * 256;
            int ch = idx >> 7, p4 = (idx & 127) * 4;
            float4 v = *(float4*)&stb[ch * 520 + p4];
            *(float4*)(out + (size_t)(b * OO + gi * 8 + ch) * HWP + p0 + p4) = v;
        }
        __syncthreads();
    }
}

// ---------------- launch ----------------
extern "C" void kernel_launch(void* const* d_in, const int* in_sizes, int n_in,
                              void* d_out, int out_size) {
    const float* x        = (const float*)d_in[0];
    const float* x_off    = (const float*)d_in[1];
    const float* w_offset = (const float*)d_in[2];
    const float* w_deform = (const float*)d_in[3];
    const float* gamma    = (const float*)d_in[4];
    const float* beta     = (const float*)d_in[5];
    float* out = (float*)d_out;

    cudaFuncSetAttribute(gemm_kernel, cudaFuncAttributeMaxDynamicSharedMemorySize,
                         GEMM_SMEM);

    wprep_kernel<<<OO * CK / 256, 256>>>(w_deform);

    dim3 tb(32, 8), tg(HWP / 32, CG / 32, BB * DGRP);
    transpose_kernel<<<tg, tb>>>(x);

    im2col_kernel<<<16384, 256>>>(x_off, w_offset);

    dim3 gg(OO / 128, MTOT / 128);
    gemm_kernel<<<gg, 256, GEMM_SMEM>>>();

    gn_kernel<<<BB * 32, 256>>>(gamma, beta, out);
}

// round 11
// speedup vs baseline: 1.4199x; 1.0001x over previous
#include <cuda_runtime.h>
#include <cuda_fp16.h>
#include <cstdint>

#define BB 8
#define CC 256
#define OO 256
#define HH 64
#define WW 64
#define DGRP 4
#define CG 64
#define KK2 9
#define CK 2304      /* C*K2 */
#define HWP 4096     /* H*W */
#define MTOT (BB * HWP)   /* 32768 */

// ---------------- scratch (device globals; no cudaMalloc allowed) ----------------
__device__ __align__(256) __half g_xT[(size_t)BB * DGRP * HWP * CG];   // 16 MB fp16
__device__ __align__(256) __half g_col[(size_t)MTOT * CK];             // 151 MB fp16
__device__ __align__(256) __half g_wK[(size_t)OO * CK];                // 1.2 MB
__device__ __align__(256) float  g_y[(size_t)MTOT * OO];               // 32 MB
__device__ __align__(256) float  g_part[(size_t)BB * 32 * 64 * 2];     // GN partials

// ---------------- helpers ----------------
__device__ __forceinline__ uint32_t smem_u32(const void* p) {
    uint32_t a;
    asm("{ .reg .u64 t; cvta.to.shared.u64 t, %1; cvt.u32.u64 %0, t; }" : "=r"(a) : "l"(p));
    return a;
}
__device__ __forceinline__ void cp16(uint32_t dst, const void* src) {
    asm volatile("cp.async.cg.shared.global [%0], [%1], 16;" :: "r"(dst), "l"(src));
}
__device__ __forceinline__ void ldsm4(uint32_t& r0, uint32_t& r1, uint32_t& r2,
                                      uint32_t& r3, uint32_t addr) {
    asm volatile("ldmatrix.sync.aligned.m8n8.x4.shared.b16 {%0,%1,%2,%3}, [%4];"
                 : "=r"(r0), "=r"(r1), "=r"(r2), "=r"(r3) : "r"(addr));
}
__device__ __forceinline__ void mma_fp16(float* d, const uint32_t* a, const uint32_t* b) {
    asm volatile(
        "mma.sync.aligned.m16n8k16.row.col.f32.f16.f16.f32 "
        "{%0,%1,%2,%3}, {%4,%5,%6,%7}, {%8,%9}, {%0,%1,%2,%3};"
        : "+f"(d[0]), "+f"(d[1]), "+f"(d[2]), "+f"(d[3])
        : "r"(a[0]), "r"(a[1]), "r"(a[2]), "r"(a[3]), "r"(b[0]), "r"(b[1]));
}

// ---------------- kernel 1: weights -> g_wK[o][ck] (K-major, fp16) ----------------
__global__ void wprep_kernel(const float* __restrict__ wd) {
    int idx = blockIdx.x * 256 + threadIdx.x;   // < OO*CK
    int o = idx / CK;
    int ck = idx - o * CK;
    int cg = ck & 63;
    int t = ck >> 6;
    int k2 = t % KK2;
    int g = t / KK2;
    g_wK[idx] = __float2half_rn(wd[((size_t)o * CC + g * CG + cg) * KK2 + k2]);
}

// ---------------- kernel 2: x[b][c][p] -> xT[b][g][p][cg] (fp16) ----------------
__global__ void transpose_kernel(const float* __restrict__ x) {
    __shared__ float tile[32][33];
    int bg = blockIdx.z;
    int c0 = blockIdx.y * 32;
    int p0 = blockIdx.x * 32;
    int tx = threadIdx.x, ty = threadIdx.y;
    const float* in = x + (size_t)bg * CG * HWP;
    __half* out = g_xT + (size_t)bg * HWP * CG;
#pragma unroll
    for (int i = 0; i < 32; i += 8)
        tile[ty + i][tx] = in[(size_t)(c0 + ty + i) * HWP + p0 + tx];
    __syncthreads();
#pragma unroll
    for (int i = 0; i < 32; i += 8)
        out[(size_t)(p0 + ty + i) * CG + c0 + tx] = __float2half_rn(tile[tx][ty + i]);
}

// ---------------- kernel 3: offsets (1x1 conv) + deformable im2col (fp16 taps) -------
// one warp per (b, g, p); handles all 9 kernel points; lane owns channel pair 2l,2l+1
__global__ void im2col_kernel(const float* __restrict__ x_off,
                              const float* __restrict__ w_offset) {
    int tid = threadIdx.x;
    int lane = tid & 31;
    int wi = blockIdx.x * 8 + (tid >> 5);   // < 131072 = B*DG*HW
    int p = wi & (HWP - 1);
    int t2 = wi >> 12;
    int g = t2 & 3;
    int b = t2 >> 2;
    int h = p >> 6, w = p & 63;

    const float* xo = x_off + (size_t)b * 4 * HWP + p;
    float ov = (lane < 4) ? xo[(size_t)lane * HWP] : 0.f;
    float o0 = __shfl_sync(0xFFFFFFFFu, ov, 0);
    float o1 = __shfl_sync(0xFFFFFFFFu, ov, 1);
    float o2 = __shfl_sync(0xFFFFFFFFu, ov, 2);
    float o3 = __shfl_sync(0xFFFFFFFFu, ov, 3);

    float comp = 0.f;
    if (lane < 18) {
        int k2c = lane % 9;
        int ax = lane / 9;
        const float* wo = w_offset + (size_t)(((g * KK2 + k2c) * 2 + ax)) * 4;
        comp = wo[0] * o0 + wo[1] * o1 + wo[2] * o2 + wo[3] * o3;
    }

    const __half* base = g_xT + (size_t)(b * DGRP + g) * HWP * CG;
    __half* dstbase = g_col + (size_t)(b * HWP + p) * CK + g * KK2 * CG;

#pragma unroll
    for (int k2 = 0; k2 < KK2; k2++) {
        float offy = __shfl_sync(0xFFFFFFFFu, comp, k2);
        float offx = __shfl_sync(0xFFFFFFFFu, comp, k2 + 9);
        float py = (float)(h + k2 / 3 - 1) + offy;
        float px = (float)(w + k2 % 3 - 1) + offx;
        float fy = floorf(py), fx = floorf(px);
        float wy = py - fy, wx = px - fx;
        int y0 = (int)fy, x0 = (int)fx;

        float w00 = (1.f - wy) * (1.f - wx);
        float w01 = (1.f - wy) * wx;
        float w10 = wy * (1.f - wx);
        float w11 = wy * wx;

        bool vy0 = (y0 >= 0) & (y0 < HH);
        bool vy1 = (y0 + 1 >= 0) & (y0 + 1 < HH);
        bool vx0 = (x0 >= 0) & (x0 < WW);
        bool vx1 = (x0 + 1 >= 0) & (x0 + 1 < WW);
        if (!(vy0 && vx0)) w00 = 0.f;
        if (!(vy0 && vx1)) w01 = 0.f;
        if (!(vy1 && vx0)) w10 = 0.f;
        if (!(vy1 && vx1)) w11 = 0.f;

        int y0c = min(max(y0, 0), HH - 1), y1c = min(max(y0 + 1, 0), HH - 1);
        int x0c = min(max(x0, 0), WW - 1), x1c = min(max(x0 + 1, 0), WW - 1);

        const __half2* p00 = (const __half2*)(base + (size_t)(y0c * WW + x0c) * CG) + lane;
        const __half2* p01 = (const __half2*)(base + (size_t)(y0c * WW + x1c) * CG) + lane;
        const __half2* p10 = (const __half2*)(base + (size_t)(y1c * WW + x0c) * CG) + lane;
        const __half2* p11 = (const __half2*)(base + (size_t)(y1c * WW + x1c) * CG) + lane;

        float2 t00 = __half22float2(*p00);
        float2 t01 = __half22float2(*p01);
        float2 t10 = __half22float2(*p10);
        float2 t11 = __half22float2(*p11);
        float vx_ = w00 * t00.x + w01 * t01.x + w10 * t10.x + w11 * t11.x;
        float vy_ = w00 * t00.y + w01 * t01.y + w10 * t10.y + w11 * t11.y;

        *(__half2*)(dstbase + k2 * CG + 2 * lane) = __floats2half2_rn(vx_, vy_);
    }
}

// ---------------- kernel 4: fp16 mma.sync GEMM + GN partial stats --------------------
// block 128x128, BK=64 halves, 8 warps (2x4), warp tile 64x32
#define BKH 64
#define LDTH 72
#define NST (CK / BKH)   /* 36 */
#define NSTAGE 3
#define STG_H (128 * LDTH)
#define GEMM_SMEM (NSTAGE * 2 * STG_H * 2)  /* 110592 B */

__global__ __launch_bounds__(256, 2) void gemm_kernel() {
    extern __shared__ __align__(16) __half dsmh[];
    __half* Asm = dsmh;
    __half* Bsm = dsmh + NSTAGE * STG_H;
    uint32_t sA0 = smem_u32(Asm);
    uint32_t sB0 = smem_u32(Bsm);

    int tid = threadIdx.x;
    int n0 = blockIdx.x * 128;
    int m0 = blockIdx.y * 128;

    int lane = tid & 31, w = tid >> 5;
    int wm = (w >> 2) * 64;   // warp m-offset (0/64)
    int wn = (w & 3) * 32;    // warp n-offset (0/32/64/96)
    int g = lane >> 2, tq = lane & 3;

    int sector = lane >> 3, rowin = lane & 7;
    int aoff[4], boff[2];
#pragma unroll
    for (int i = 0; i < 4; i++)
        aoff[i] = (wm + i * 16 + (sector & 1) * 8 + rowin) * LDTH + (sector >> 1) * 8;
#pragma unroll
    for (int jp = 0; jp < 2; jp++)
        boff[jp] = (wn + jp * 16 + (sector & 1) * 8 + rowin) * LDTH + (sector >> 1) * 8;

    int cr[4], cc[4];
#pragma unroll
    for (int q = 0; q < 4; q++) {
        int task = tid + q * 256;
        cr[q] = task >> 3;
        cc[q] = (task & 7) * 8;
    }

    float acc[4][4][4];
#pragma unroll
    for (int i = 0; i < 4; i++)
#pragma unroll
        for (int jj = 0; jj < 4; jj++)
#pragma unroll
            for (int e = 0; e < 4; e++) acc[i][jj][e] = 0.f;

#pragma unroll
    for (int s = 0; s < NSTAGE - 1; s++) {
        int k0 = s * BKH;
        uint32_t a_base = sA0 + (uint32_t)(s * STG_H * 2);
        uint32_t b_base = sB0 + (uint32_t)(s * STG_H * 2);
#pragma unroll
        for (int q = 0; q < 4; q++) {
            cp16(a_base + (uint32_t)(cr[q] * LDTH + cc[q]) * 2,
                 g_col + (size_t)(m0 + cr[q]) * CK + k0 + cc[q]);
            cp16(b_base + (uint32_t)(cr[q] * LDTH + cc[q]) * 2,
                 g_wK + (size_t)(n0 + cr[q]) * CK + k0 + cc[q]);
        }
        asm volatile("cp.async.commit_group;" ::: "memory");
    }

    int buf = 0;
    for (int s = 0; s < NST; s++) {
        if (s + 1 < NST) {
            asm volatile("cp.async.wait_group 1;" ::: "memory");
        } else {
            asm volatile("cp.async.wait_group 0;" ::: "memory");
        }
        __syncthreads();

        if (s + 2 < NST) {
            int nb = buf + 2 >= NSTAGE ? buf + 2 - NSTAGE : buf + 2;
            int k0 = (s + 2) * BKH;
            uint32_t a_base = sA0 + (uint32_t)(nb * STG_H * 2);
            uint32_t b_base = sB0 + (uint32_t)(nb * STG_H * 2);
#pragma unroll
            for (int q = 0; q < 4; q++) {
                cp16(a_base + (uint32_t)(cr[q] * LDTH + cc[q]) * 2,
                     g_col + (size_t)(m0 + cr[q]) * CK + k0 + cc[q]);
                cp16(b_base + (uint32_t)(cr[q] * LDTH + cc[q]) * 2,
                     g_wK + (size_t)(n0 + cr[q]) * CK + k0 + cc[q]);
            }
            asm volatile("cp.async.commit_group;" ::: "memory");
        }

        uint32_t abuf = sA0 + (uint32_t)(buf * STG_H * 2);
        uint32_t bbuf = sB0 + (uint32_t)(buf * STG_H * 2);
#pragma unroll
        for (int ks = 0; ks < 4; ks++) {
            uint32_t af[4][4], q0, q1, q2, q3;
            uint32_t bf[4][2];
            uint32_t kofs = (uint32_t)(ks * 16) * 2;
#pragma unroll
            for (int i = 0; i < 4; i++)
                ldsm4(af[i][0], af[i][1], af[i][2], af[i][3],
                      abuf + kofs + (uint32_t)aoff[i] * 2);
#pragma unroll
            for (int jp = 0; jp < 2; jp++) {
                ldsm4(q0, q1, q2, q3, bbuf + kofs + (uint32_t)boff[jp] * 2);
                bf[jp * 2][0] = q0; bf[jp * 2][1] = q2;
                bf[jp * 2 + 1][0] = q1; bf[jp * 2 + 1][1] = q3;
            }
#pragma unroll
            for (int i = 0; i < 4; i++)
#pragma unroll
                for (int jj = 0; jj < 4; jj++) mma_fp16(acc[i][jj], af[i], bf[jj]);
        }

        buf = buf + 1 >= NSTAGE ? 0 : buf + 1;
    }

    // ---- epilogue: write y (NHWC) + deterministic GN partial stats ----
#pragma unroll
    for (int i = 0; i < 4; i++) {
#pragma unroll
        for (int jj = 0; jj < 4; jj++) {
            int row = m0 + wm + i * 16 + g;
            int col = n0 + wn + jj * 8 + 2 * tq;
            float2 v0 = make_float2(acc[i][jj][0], acc[i][jj][1]);
            float2 v1 = make_float2(acc[i][jj][2], acc[i][jj][3]);
            *(float2*)(g_y + (size_t)row * OO + col) = v0;
            *(float2*)(g_y + (size_t)(row + 8) * OO + col) = v1;
        }
    }
    // each warp's jj block is exactly one 8-channel GN group
    int b = blockIdx.y >> 5;
    int mtile = blockIdx.y & 31;
    int slot = mtile * 2 + (w >> 2);
#pragma unroll
    for (int jj = 0; jj < 4; jj++) {
        float s = 0.f, ss = 0.f;
#pragma unroll
        for (int i = 0; i < 4; i++)
#pragma unroll
            for (int e = 0; e < 4; e++) {
                float v = acc[i][jj][e];
                s += v;
                ss += v * v;
            }
#pragma unroll
        for (int off = 16; off; off >>= 1) {
            s += __shfl_xor_sync(0xFFFFFFFFu, s, off);
            ss += __shfl_xor_sync(0xFFFFFFFFu, ss, off);
        }
        if (lane == 0) {
            int gi = (n0 + wn + jj * 8) >> 3;
            float* dst = g_part + (((size_t)b * 32 + gi) * 64 + slot) * 2;
            dst[0] = s;
            dst[1] = ss;
        }
    }
}

// ---------------- kernel 5: GroupNorm + ReLU + NHWC->NCHW (single pass) --------------
__global__ void gn_kernel(const float* __restrict__ gamma,
                          const float* __restrict__ beta, float* __restrict__ out) {
    int b = blockIdx.x >> 5;
    int gi = blockIdx.x & 31;
    int tid = threadIdx.x;   // 256
    const float* yb = g_y + (size_t)b * HWP * OO;

    // reduce the 64 precomputed partials
    float s = 0.f, ss = 0.f;
    if (tid < 64) {
        const float* pp = g_part + (((size_t)b * 32 + gi) * 64 + tid) * 2;
        s = pp[0];
        ss = pp[1];
    }
    __shared__ float rs[256], rss[256];
    rs[tid] = s;
    rss[tid] = ss;
    __syncthreads();
    for (int st = 128; st > 0; st >>= 1) {
        if (tid < st) {
            rs[tid] += rs[tid + st];
            rss[tid] += rss[tid + st];
        }
        __syncthreads();
    }
    float mu = rs[0] * (1.f / 32768.f);
    float var = rss[0] * (1.f / 32768.f) - mu * mu;
    float rstd = rsqrtf(var + 1e-5f);

    float ga[8], be[8];
#pragma unroll
    for (int j = 0; j < 8; j++) {
        int o = gi * 8 + j;
        ga[j] = gamma[o] * rstd;
        be[j] = beta[o] - mu * ga[j];
    }

    __shared__ float stb[8 * 520];   // [ch][520]
    for (int p0 = 0; p0 < HWP; p0 += 512) {
#pragma unroll
        for (int q = 0; q < 2; q++) {
            int pp = tid * 2 + q;   // 0..511
            const float* src = yb + (size_t)(p0 + pp) * OO + gi * 8;
            float4 v0 = *(const float4*)src;
            float4 v1 = *(const float4*)(src + 4);
            float r[8] = {v0.x, v0.y, v0.z, v0.w, v1.x, v1.y, v1.z, v1.w};
#pragma unroll
            for (int j = 0; j < 8; j++)
                stb[j * 520 + pp] = fmaxf(fmaf(r[j], ga[j], be[j]), 0.f);
        }
        __syncthreads();
#pragma unroll
        for (int q = 0; q < 4; q++) {
            int idx = tid + q * 256;
            int ch = idx >> 7, p4 = (idx & 127) * 4;
            float4 v = *(float4*)&stb[ch * 520 + p4];
            *(float4*)(out + (size_t)(b * OO + gi * 8 + ch) * HWP + p0 + p4) = v;
        }
        __syncthreads();
    }
}

// ---------------- launch ----------------
extern "C" void kernel_launch(void* const* d_in, const int* in_sizes, int n_in,
                              void* d_out, int out_size) {
    const float* x        = (const float*)d_in[0];
    const float* x_off    = (const float*)d_in[1];
    const float* w_offset = (const float*)d_in[2];
    const float* w_deform = (const float*)d_in[3];
    const float* gamma    = (const float*)d_in[4];
    const float* beta     = (const float*)d_in[5];
    float* out = (float*)d_out;

    cudaFuncSetAttribute(gemm_kernel, cudaFuncAttributeMaxDynamicSharedMemorySize,
                         GEMM_SMEM);

    wprep_kernel<<<OO * CK / 256, 256>>>(w_deform);

    dim3 tb(32, 8), tg(HWP / 32, CG / 32, BB * DGRP);
    transpose_kernel<<<tg, tb>>>(x);

    im2col_kernel<<<16384, 256>>>(x_off, w_offset);

    dim3 gg(OO / 128, MTOT / 128);
    gemm_kernel<<<gg, 256, GEMM_SMEM>>>();

    gn_kernel<<<BB * 32, 256>>>(gamma, beta, out);
}